// round 15
// baseline (speedup 1.0000x reference)
#include <cuda_runtime.h>
#include <math.h>

#define NB 8
#define FH 120
#define FW 160
#define NPIX (FH*FW)
#define NSEM 16
#define NC 20
#define MS 480
#define MS2 (MS*MS)
#define TCH 18            // tile channels: 0=fp_map, 1=fp_exp, 2..17=sem
#define HPC 20            // padded interleaved hp channels (5 x float4)
#define VRD 100
#define CELLS (VRD*VRD)
#define RB 160            // compact rot tile side (max translated span ~156)
#define RB2 (RB*RB)

// block partition
#define SPLAT_BLKS 600                    // 600*256 == NB*NPIX exactly
#define ROT_BLKS   (100*NB*3)             // 2400
#define NXA 40                            // copy row-groups in k2 (rows 0..159)
#define NXB 20                            // copy row-groups in k3 (rows 160..239)
#define NXC 60                            // copy row-groups in k4 (rows 240..479)
#define COPY1_BLKS (NXA*19*NB)            // 6080
#define COPY2_BLKS (NXB*19*NB)            // 3040
#define COPY3_BLKS (NXC*19*NB)            // 9120
#define BLEND_BLKS (40*TCH*NB)            // 5760

// scratch (static device memory: allowed)
__device__ float4 g_hp4[(size_t)NB*CELLS*5];          // 6.4 MB, L2-resident
__device__ float  g_rotc[(size_t)NB*TCH*RB2];         // compact rotated planes
__device__ int    g_bbox[NB][8];                      // [0..3] rot bbox ; [4..7] translated bbox

__device__ __forceinline__ void red_v4(float* p, float a, float b, float c, float d) {
    asm volatile("red.global.add.v4.f32 [%0], {%1, %2, %3, %4};"
                 :: "l"(p), "f"(a), "f"(b), "f"(c), "f"(d) : "memory");
}

// bbox + translated bbox (8 threads of block 0) + zero g_hp4 (all threads)
__global__ void k_bbox_zero(const float* __restrict__ poses) {
    size_t i = blockIdx.x*(size_t)blockDim.x + threadIdx.x;
    if (i < (size_t)NB*CELLS*5) g_hp4[i] = make_float4(0.f, 0.f, 0.f, 0.f);
    if (blockIdx.x != 0 || threadIdx.x >= NB) return;
    int b = threadIdx.x;
    float th = (90.0f - poses[b*3+2]) * 0.017453292519943295f;
    float ct = cosf(th), st = sinf(th);
    const float gxlo = 189.0f/239.5f - 1.0f, gxhi = 290.0f/239.5f - 1.0f;
    const float gylo = 239.0f/239.5f - 1.0f, gyhi = 340.0f/239.5f - 1.0f;
    float gxs[2] = {gxlo, gxhi}, gys[2] = {gylo, gyhi};
    float xmn = 1e9f, xmx = -1e9f, ymn = 1e9f, ymx = -1e9f;
    #pragma unroll
    for (int a = 0; a < 2; a++)
        #pragma unroll
        for (int c = 0; c < 2; c++) {
            float gx = gxs[a], gy = gys[c];
            float x =  ct*gx + st*gy;
            float y = -st*gx + ct*gy;
            xmn = fminf(xmn, x); xmx = fmaxf(xmx, x);
            ymn = fminf(ymn, y); ymx = fmaxf(ymx, y);
        }
    int jmn = (int)floorf((xmn + 1.0f)*240.0f - 0.5f) - 2;
    int jmx = (int)ceilf ((xmx + 1.0f)*240.0f - 0.5f) + 2;
    int imn = (int)floorf((ymn + 1.0f)*240.0f - 0.5f) - 2;
    int imx = (int)ceilf ((ymx + 1.0f)*240.0f - 0.5f) + 2;
    int i0 = max(imn, 0), i1 = min(imx, MS-1);
    int j0 = max(jmn, 0), j1 = min(jmx, MS-1);
    g_bbox[b][0] = i0; g_bbox[b][1] = i1;
    g_bbox[b][2] = j0; g_bbox[b][3] = j1;

    float pxp = poses[b*3+0], pyp = poses[b*3+1];
    float stx = -((pxp*100.0f)/5.0f - 240.0f)/240.0f;
    float sty = -((pyp*100.0f)/5.0f - 240.0f)/240.0f;
    const float A = 239.5f/240.0f;
    float cy = 239.5f/480.0f + 239.5f*sty;
    int ti0 = (int)floorf(((float)(i0-1) - cy)/A) - 1;
    int ti1 = (int)ceilf (((float)(i1+1) - cy)/A) + 1;
    float cx = 239.5f/480.0f + 239.5f*stx;
    int tj0 = (int)floorf(((float)(j0-1) - cx)/A) - 1;
    int tj1 = (int)ceilf (((float)(j1+1) - cx)/A) + 1;
    g_bbox[b][4] = max(ti0, 0); g_bbox[b][5] = min(ti1, MS-1);
    g_bbox[b][6] = max(tj0, 0); g_bbox[b][7] = min(tj1, MS-1);
}

// ---- bodies ---------------------------------------------------------------

__device__ __forceinline__ void splat_body(int t, const float* __restrict__ obs, float f_cam) {
    int b = t / NPIX, pix = t % NPIX;
    int i = pix / FW, j = pix % FW;
    const float* ob = obs + (size_t)b*NC*NPIX;

    float d = ob[3*NPIX + pix] * 100.0f;               // depth cm (inputs never 0)
    float X = ((float)j - 79.5f) * d / f_cam + 250.0f;
    float Z = ((float)(FH-1-i) - 59.5f) * d / f_cam + 88.0f;
    float pos0 = X / 5.0f;
    float pos1 = d / 5.0f;
    float pos2 = Z / 5.0f + 8.0f;

    float fl0 = floorf(pos0), fl1 = floorf(pos1), fl2 = floorf(pos2);
    float p0f[2] = {fl0, fl0+1.0f}, p1f[2] = {fl1, fl1+1.0f};
    float w0[2], w1[2];
    #pragma unroll
    for (int k = 0; k < 2; k++) {
        w0[k] = (1.0f - fabsf(pos0 - p0f[k])) * ((p0f[k] > 0.0f && p0f[k] < 100.0f) ? 1.0f : 0.0f);
        w1[k] = (1.0f - fabsf(pos1 - p1f[k])) * ((p1f[k] > 0.0f && p1f[k] < 100.0f) ? 1.0f : 0.0f);
    }
    float wze = 0.0f, wza = 0.0f;
    #pragma unroll
    for (int k = 0; k < 2; k++) {
        float p = fl2 + (float)k;
        if (p > 0.0f && p < 80.0f) {
            float wz = 1.0f - fabsf(pos2 - p);
            wze += wz;
            int zi = (int)p;
            if (zi >= 13 && zi < 25) wza += wz;
        }
    }
    if (wze <= 0.0f && wza <= 0.0f) return;
    if (w0[0] == 0.0f && w0[1] == 0.0f) return;
    if (w1[0] == 0.0f && w1[1] == 0.0f) return;

    bool agent = (wza > 0.0f);
    float sem[NSEM];
    #pragma unroll
    for (int s = 0; s < NSEM; s++) sem[s] = 0.0f;
    if (agent) {
        #pragma unroll
        for (int s = 0; s < NSEM; s++) sem[s] = ob[(4+s)*NPIX + pix];
    }

    float* hpb = (float*)(g_hp4 + (size_t)b*CELLS*5);
    #pragma unroll
    for (int a = 0; a < 2; a++) {
        if (w0[a] == 0.0f) continue;
        int ix = (int)p0f[a];
        #pragma unroll
        for (int c2 = 0; c2 < 2; c2++) {
            if (w1[c2] == 0.0f) continue;
            int iy = (int)p1f[c2];
            float wxy = w0[a]*w1[c2];
            float wag = wxy*wza;
            float* cp = hpb + (size_t)(iy*VRD + ix)*HPC;
            red_v4(cp, wxy*wze, wag, wag*sem[0], wag*sem[1]);
            if (agent) {
                red_v4(cp+4,  wag*sem[2],  wag*sem[3],  wag*sem[4],  wag*sem[5]);
                red_v4(cp+8,  wag*sem[6],  wag*sem[7],  wag*sem[8],  wag*sem[9]);
                red_v4(cp+12, wag*sem[10], wag*sem[11], wag*sem[12], wag*sem[13]);
                red_v4(cp+16, wag*sem[14], wag*sem[15], 0.0f, 0.0f);
            }
        }
    }
}

__device__ __forceinline__ void rotate_body(int t, int b, int grp, const float* __restrict__ poses) {
    int i0 = g_bbox[b][0], i1 = g_bbox[b][1], j0 = g_bbox[b][2], j1 = g_bbox[b][3];
    int w  = j1 - j0 + 1, h = i1 - i0 + 1;
    int li = t / w, lj = t % w;
    if (li >= h) return;
    int r = i0 + li, col = j0 + lj;

    float th = (90.0f - poses[b*3+2]) * 0.017453292519943295f;
    float ct = cosf(th), st = sinf(th);
    float x = (2.0f*col + 1.0f)/480.0f - 1.0f;
    float y = (2.0f*r   + 1.0f)/480.0f - 1.0f;
    float gx = ct*x - st*y;
    float gy = st*x + ct*y;
    float xs = (gx + 1.0f)*0.5f*479.0f;
    float ys = (gy + 1.0f)*0.5f*479.0f;
    float x0f = floorf(xs), y0f = floorf(ys);

    float wyv[2], wxv[2];
    int   lyi[2], lxi[2];
    #pragma unroll
    for (int k = 0; k < 2; k++) {
        float pyf = y0f + (float)k;
        int   yi  = (int)pyf;
        bool  ok  = (pyf >= 0.0f && pyf < 480.0f) && (yi >= 240 && yi < 340);
        wyv[k] = ok ? (1.0f - fabsf(ys - pyf)) : 0.0f;
        lyi[k] = min(max(yi - 240, 0), VRD-1);
        float pxf = x0f + (float)k;
        int   xi  = (int)pxf;
        bool  okx = (pxf >= 0.0f && pxf < 480.0f) && (xi >= 190 && xi < 290);
        wxv[k] = okx ? (1.0f - fabsf(xs - pxf)) : 0.0f;
        lxi[k] = min(max(xi - 190, 0), VRD-1);
    }

    float acc[6];
    #pragma unroll
    for (int c = 0; c < 6; c++) acc[c] = 0.0f;
    int q0 = (grp == 0) ? 0 : (grp == 1) ? 1 : 3;
    int q1 = q0 + 1;

    const float4* hpb = g_hp4 + (size_t)b*CELLS*5;
    #pragma unroll
    for (int dy = 0; dy < 2; dy++) {
        #pragma unroll
        for (int dx = 0; dx < 2; dx++) {
            float wgt = wxv[dx]*wyv[dy];
            const float4* cp = hpb + (size_t)(lyi[dy]*VRD + lxi[dx])*5;
            float4 ta = cp[q0], tb = cp[q1];
            if (grp == 0) {
                acc[0] += wgt * fminf(ta.y, 1.0f);
                acc[1] += wgt * fminf(ta.x, 1.0f);
                acc[2] += wgt * fminf(ta.z*0.2f, 1.0f);
                acc[3] += wgt * fminf(ta.w*0.2f, 1.0f);
                acc[4] += wgt * fminf(tb.x*0.2f, 1.0f);
                acc[5] += wgt * fminf(tb.y*0.2f, 1.0f);
            } else if (grp == 1) {
                acc[0] += wgt * fminf(ta.z*0.2f, 1.0f);
                acc[1] += wgt * fminf(ta.w*0.2f, 1.0f);
                acc[2] += wgt * fminf(tb.x*0.2f, 1.0f);
                acc[3] += wgt * fminf(tb.y*0.2f, 1.0f);
                acc[4] += wgt * fminf(tb.z*0.2f, 1.0f);
                acc[5] += wgt * fminf(tb.w*0.2f, 1.0f);
            } else {
                acc[0] += wgt * fminf(ta.x*0.2f, 1.0f);
                acc[1] += wgt * fminf(ta.y*0.2f, 1.0f);
                acc[2] += wgt * fminf(ta.z*0.2f, 1.0f);
                acc[3] += wgt * fminf(ta.w*0.2f, 1.0f);
                acc[4] += wgt * fminf(tb.x*0.2f, 1.0f);
                acc[5] += wgt * fminf(tb.y*0.2f, 1.0f);
            }
        }
    }
    float* rp = g_rotc + (size_t)b*TCH*RB2 + (size_t)(grp*6)*RB2 + (size_t)li*RB + lj;
    #pragma unroll
    for (int c = 0; c < 6; c++) rp[(size_t)c*RB2] = acc[c];
}

// copy one row-quarter; SKIPS float4 groups inside the translated window for
// blended channels (blend writes those disjointly). ch2/ch3 never blended.
__device__ __forceinline__ void copy_body(int b, int cp_, int r, int t,
                                          const float* __restrict__ ml,
                                          const float* __restrict__ poses,
                                          float* __restrict__ out) {
    if (t >= 60) return;
    int c = (cp_ < 2) ? cp_ : cp_ + 1;
    int colA = t << 2, colB = colA + 240;
    size_t rbase = (size_t)r*MS;
    if (c == 3) {
        size_t m3 = ((size_t)b*NC + 3)*MS2 + rbase;
        size_t m2 = ((size_t)b*NC + 2)*MS2 + rbase;
        float4 vA = *(const float4*)(ml + m3 + colA);
        float4 vB = *(const float4*)(ml + m3 + colB);
        *(float4*)(out + m2 + colA) = vA;   // ch2 = pre-mask ch3
        *(float4*)(out + m2 + colB) = vB;
        float pxp = poses[b*3+0], pyp = poses[b*3+1];
        int rr = (int)(pyp*100.0f/5.0f);
        int cc = (int)(pxp*100.0f/5.0f);
        if (abs(r - rr) <= 1) {
            float* a = &vA.x; float* bb = &vB.x;
            #pragma unroll
            for (int p = 0; p < 4; p++) {
                if (abs(colA+p - cc) <= 1) a[p] = 1.0f;
                if (abs(colB+p - cc) <= 1) bb[p] = 1.0f;
            }
        }
        *(float4*)(out + m3 + colA) = vA;
        *(float4*)(out + m3 + colB) = vB;
        return;
    }
    int ti0 = g_bbox[b][4], ti1 = g_bbox[b][5];
    int tj0a = g_bbox[b][6] & ~3, tj1 = g_bbox[b][7];
    bool rowAct = (r >= ti0 && r <= ti1);
    bool skipA = rowAct && (colA >= tj0a && colA <= tj1);
    bool skipB = rowAct && (colB >= tj0a && colB <= tj1);
    size_t mbase = ((size_t)b*NC + c)*MS2 + rbase;
    if (!skipA) {
        float4 mA = *(const float4*)(ml + mbase + colA);
        *(float4*)(out + mbase + colA) = mA;
    }
    if (!skipB) {
        float4 mB = *(const float4*)(ml + mbase + colB);
        *(float4*)(out + mbase + colB) = mB;
    }
}

// blend: write out = max(maps_last, translated) for EXACTLY the skipped groups.
// Depends only on rotate + bbox (disjoint writes from copy).
__device__ __forceinline__ void blend_body(int b, int ch, int xb, int tx, int ty,
                                           const float* __restrict__ ml,
                                           const float* __restrict__ poses,
                                           float* __restrict__ out) {
    if (tx >= 40) return;
    int ti0 = g_bbox[b][4], ti1 = g_bbox[b][5];
    int tj0a = g_bbox[b][6] & ~3, tj1 = g_bbox[b][7];
    int r = ti0 + xb*4 + ty;
    if (r > ti1) return;
    int col0 = tj0a + (tx << 2);
    if (col0 > tj1) return;

    int oc = (ch < 2) ? ch : ch + 2;
    size_t obase = ((size_t)b*NC + oc)*MS2 + (size_t)r*MS + col0;
    float4 o = *(const float4*)(ml + obase);

    float pxp = poses[b*3+0], pyp = poses[b*3+1];
    float stx = -((pxp*100.0f)/5.0f - 240.0f)/240.0f;
    float sty = -((pyp*100.0f)/5.0f - 240.0f)/240.0f;

    float ys  = ((2.0f*r + 1.0f)/480.0f + sty)*0.5f*479.0f;
    float y0f = floorf(ys);
    float wy0 = (y0f + 1.0f) - ys;
    float wy1 = ys - y0f;
    int   ry0 = (int)y0f, ry1 = ry0 + 1;
    int i0 = g_bbox[b][0], i1 = g_bbox[b][1], j0 = g_bbox[b][2], j1 = g_bbox[b][3];
    bool vy0 = (y0f      >= 0.0f && y0f      < 480.0f) && ry0 >= i0 && ry0 <= i1;
    bool vy1 = (y0f+1.0f >= 0.0f && y0f+1.0f < 480.0f) && ry1 >= i0 && ry1 <= i1;

    if (vy0 || vy1) {
        const float* base = g_rotc + ((size_t)b*TCH + ch)*RB2;
        int ly0 = min(max(ry0 - i0, 0), RB-1);
        int ly1 = min(max(ry1 - i0, 0), RB-1);
        const float* row0 = base + (size_t)ly0*RB;
        const float* row1 = base + (size_t)ly1*RB;
        const float XSTEP = 479.0f/480.0f;
        float xs_base = ((2.0f*col0 + 1.0f)/480.0f + stx)*0.5f*479.0f;
        float* of = &o.x;
        #pragma unroll
        for (int p = 0; p < 4; p++) {
            float xs  = fmaf((float)p, XSTEP, xs_base);
            float x0f = floorf(xs);
            float wx1 = xs - x0f;
            float wx0 = 1.0f - wx1;
            int   cx0 = (int)x0f;
            bool vx0 = (x0f      >= 0.0f && x0f      < 480.0f) && cx0   >= j0 && cx0   <= j1;
            bool vx1 = (x0f+1.0f >= 0.0f && x0f+1.0f < 480.0f) && cx0+1 >= j0 && cx0+1 <= j1;
            if (!(vx0 || vx1)) continue;
            int lx0 = min(max(cx0 - j0, 0), RB-2);
            float acc = 0.0f;
            if (vy0) {
                if (vx0) acc += wx0*wy0*row0[lx0];
                if (vx1) acc += wx1*wy0*row0[lx0+1];
            }
            if (vy1) {
                if (vx0) acc += wx0*wy1*row1[lx0];
                if (vx1) acc += wx1*wy1*row1[lx0+1];
            }
            of[p] = fmaxf(of[p], acc);
        }
    }
    *(float4*)(out + obase) = o;
}

// ---- fused kernels ---------------------------------------------------------

// k2: splat || copy rows 0..159
__global__ void __launch_bounds__(256) k_splat_copy(const float* __restrict__ obs,
                                                    const float* __restrict__ maps_last,
                                                    const float* __restrict__ poses,
                                                    float* __restrict__ out,
                                                    float f_cam) {
    int gid = blockIdx.x;
    if (gid < SPLAT_BLKS) {
        int tid = threadIdx.x + 64*threadIdx.y;
        splat_body(gid*256 + tid, obs, f_cam);
        return;
    }
    int cid = gid - SPLAT_BLKS;
    int xb  = cid % NXA;
    int cp_ = (cid / NXA) % 19;
    int b   = cid / (NXA*19);
    copy_body(b, cp_, xb*4 + threadIdx.y, threadIdx.x, maps_last, poses, out);
}

// k3: rotate || copy rows 160..239
__global__ void __launch_bounds__(256) k_rot_copy(const float* __restrict__ maps_last,
                                                  const float* __restrict__ poses,
                                                  float* __restrict__ out) {
    int gid = blockIdx.x;
    if (gid < ROT_BLKS) {
        int tid = threadIdx.x + 64*threadIdx.y;
        int bx  = gid % 100;
        int b   = (gid / 100) % NB;
        int grp = gid / 800;
        rotate_body(bx*256 + tid, b, grp, poses);
        return;
    }
    int cid = gid - ROT_BLKS;
    int xb  = NXA + cid % NXB;
    int cp_ = (cid / NXB) % 19;
    int b   = cid / (NXB*19);
    copy_body(b, cp_, xb*4 + threadIdx.y, threadIdx.x, maps_last, poses, out);
}

// k4: blend || copy rows 240..479
__global__ void __launch_bounds__(256) k_blend_copy(const float* __restrict__ maps_last,
                                                    const float* __restrict__ poses,
                                                    float* __restrict__ out) {
    int gid = blockIdx.x;
    if (gid < BLEND_BLKS) {
        int xb = gid % 40;
        int ch = (gid / 40) % TCH;
        int b  = gid / (40*TCH);
        blend_body(b, ch, xb, threadIdx.x, threadIdx.y, maps_last, poses, out);
        return;
    }
    int cid = gid - BLEND_BLKS;
    int xb  = NXA + NXB + cid % NXC;
    int cp_ = (cid / NXC) % 19;
    int b   = cid / (NXC*19);
    copy_body(b, cp_, xb*4 + threadIdx.y, threadIdx.x, maps_last, poses, out);
}

extern "C" void kernel_launch(void* const* d_in, const int* in_sizes, int n_in,
                              void* d_out, int out_size) {
    const float* obs       = (const float*)d_in[0];   // (8,20,120,160)
    const float* maps_last = (const float*)d_in[1];   // (8,20,480,480)
    const float* poses     = (const float*)d_in[2];   // (8,3)
    float* out = (float*)d_out;                       // (8,20,480,480)

    float f_cam = (float)((double)FW / 2.0 / tan(79.0/2.0 * 3.14159265358979323846/180.0));

    k_bbox_zero <<<((NB*CELLS*5) + 255)/256, 256>>>(poses);
    k_splat_copy<<<SPLAT_BLKS + COPY1_BLKS, dim3(64,4)>>>(obs, maps_last, poses, out, f_cam);
    k_rot_copy  <<<ROT_BLKS + COPY2_BLKS,   dim3(64,4)>>>(maps_last, poses, out);
    k_blend_copy<<<BLEND_BLKS + COPY3_BLKS, dim3(64,4)>>>(maps_last, poses, out);
}

// round 16
// speedup vs baseline: 1.0926x; 1.0926x over previous
#include <cuda_runtime.h>
#include <math.h>

#define NB 8
#define FH 120
#define FW 160
#define NPIX (FH*FW)
#define NSEM 16
#define NC 20
#define MS 480
#define MS2 (MS*MS)
#define TCH 18            // tile channels: 0=fp_map, 1=fp_exp, 2..17=sem
#define HPC 20            // padded interleaved hp channels (5 x float4)
#define VRD 100
#define CELLS (VRD*VRD)
#define RB 160            // compact rot tile side (max translated span ~156)
#define RB2 (RB*RB)

// block partition
#define SPLAT_BLKS 600                    // 600*256 == NB*NPIX exactly
#define ROT_BLKS   (100*NB*3)             // 2400
#define COPYH_BLKS (60*19*NB)             // 9120 (half of the 120 row-groups)

// scratch (static device memory: allowed)
__device__ float4 g_hp4[(size_t)NB*CELLS*5];          // 6.4 MB, L2-resident
__device__ float  g_rotc[(size_t)NB*TCH*RB2];         // compact rotated planes
__device__ int    g_bbox[NB][8];                      // [0..3] rot bbox ; [4..7] translated bbox

__device__ __forceinline__ void red_v4(float* p, float a, float b, float c, float d) {
    asm volatile("red.global.add.v4.f32 [%0], {%1, %2, %3, %4};"
                 :: "l"(p), "f"(a), "f"(b), "f"(c), "f"(d) : "memory");
}

// bbox + translated bbox (8 threads of block 0) + zero g_hp4 (all threads)
__global__ void k_bbox_zero(const float* __restrict__ poses) {
    size_t i = blockIdx.x*(size_t)blockDim.x + threadIdx.x;
    if (i < (size_t)NB*CELLS*5) g_hp4[i] = make_float4(0.f, 0.f, 0.f, 0.f);
    if (blockIdx.x != 0 || threadIdx.x >= NB) return;
    int b = threadIdx.x;
    float th = (90.0f - poses[b*3+2]) * 0.017453292519943295f;
    float ct = cosf(th), st = sinf(th);
    const float gxlo = 189.0f/239.5f - 1.0f, gxhi = 290.0f/239.5f - 1.0f;
    const float gylo = 239.0f/239.5f - 1.0f, gyhi = 340.0f/239.5f - 1.0f;
    float gxs[2] = {gxlo, gxhi}, gys[2] = {gylo, gyhi};
    float xmn = 1e9f, xmx = -1e9f, ymn = 1e9f, ymx = -1e9f;
    #pragma unroll
    for (int a = 0; a < 2; a++)
        #pragma unroll
        for (int c = 0; c < 2; c++) {
            float gx = gxs[a], gy = gys[c];
            float x =  ct*gx + st*gy;
            float y = -st*gx + ct*gy;
            xmn = fminf(xmn, x); xmx = fmaxf(xmx, x);
            ymn = fminf(ymn, y); ymx = fmaxf(ymx, y);
        }
    int jmn = (int)floorf((xmn + 1.0f)*240.0f - 0.5f) - 2;
    int jmx = (int)ceilf ((xmx + 1.0f)*240.0f - 0.5f) + 2;
    int imn = (int)floorf((ymn + 1.0f)*240.0f - 0.5f) - 2;
    int imx = (int)ceilf ((ymx + 1.0f)*240.0f - 0.5f) + 2;
    int i0 = max(imn, 0), i1 = min(imx, MS-1);
    int j0 = max(jmn, 0), j1 = min(jmx, MS-1);
    g_bbox[b][0] = i0; g_bbox[b][1] = i1;
    g_bbox[b][2] = j0; g_bbox[b][3] = j1;

    float pxp = poses[b*3+0], pyp = poses[b*3+1];
    float stx = -((pxp*100.0f)/5.0f - 240.0f)/240.0f;
    float sty = -((pyp*100.0f)/5.0f - 240.0f)/240.0f;
    const float A = 239.5f/240.0f;
    float cy = 239.5f/480.0f + 239.5f*sty;
    int ti0 = (int)floorf(((float)(i0-1) - cy)/A) - 1;
    int ti1 = (int)ceilf (((float)(i1+1) - cy)/A) + 1;
    float cx = 239.5f/480.0f + 239.5f*stx;
    int tj0 = (int)floorf(((float)(j0-1) - cx)/A) - 1;
    int tj1 = (int)ceilf (((float)(j1+1) - cx)/A) + 1;
    g_bbox[b][4] = max(ti0, 0); g_bbox[b][5] = min(ti1, MS-1);
    g_bbox[b][6] = max(tj0, 0); g_bbox[b][7] = min(tj1, MS-1);
}

// ---- bodies ---------------------------------------------------------------

__device__ __forceinline__ void splat_body(int t, const float* __restrict__ obs, float f_cam) {
    int b = t / NPIX, pix = t % NPIX;
    int i = pix / FW, j = pix % FW;
    const float* ob = obs + (size_t)b*NC*NPIX;

    float d = ob[3*NPIX + pix] * 100.0f;               // depth cm (inputs never 0)
    float X = ((float)j - 79.5f) * d / f_cam + 250.0f;
    float Z = ((float)(FH-1-i) - 59.5f) * d / f_cam + 88.0f;
    float pos0 = X / 5.0f;
    float pos1 = d / 5.0f;
    float pos2 = Z / 5.0f + 8.0f;

    float fl0 = floorf(pos0), fl1 = floorf(pos1), fl2 = floorf(pos2);
    float p0f[2] = {fl0, fl0+1.0f}, p1f[2] = {fl1, fl1+1.0f};
    float w0[2], w1[2];
    #pragma unroll
    for (int k = 0; k < 2; k++) {
        w0[k] = (1.0f - fabsf(pos0 - p0f[k])) * ((p0f[k] > 0.0f && p0f[k] < 100.0f) ? 1.0f : 0.0f);
        w1[k] = (1.0f - fabsf(pos1 - p1f[k])) * ((p1f[k] > 0.0f && p1f[k] < 100.0f) ? 1.0f : 0.0f);
    }
    float wze = 0.0f, wza = 0.0f;
    #pragma unroll
    for (int k = 0; k < 2; k++) {
        float p = fl2 + (float)k;
        if (p > 0.0f && p < 80.0f) {
            float wz = 1.0f - fabsf(pos2 - p);
            wze += wz;
            int zi = (int)p;
            if (zi >= 13 && zi < 25) wza += wz;
        }
    }
    if (wze <= 0.0f && wza <= 0.0f) return;
    if (w0[0] == 0.0f && w0[1] == 0.0f) return;
    if (w1[0] == 0.0f && w1[1] == 0.0f) return;

    bool agent = (wza > 0.0f);
    float sem[NSEM];
    #pragma unroll
    for (int s = 0; s < NSEM; s++) sem[s] = 0.0f;
    if (agent) {
        #pragma unroll
        for (int s = 0; s < NSEM; s++) sem[s] = ob[(4+s)*NPIX + pix];
    }

    float* hpb = (float*)(g_hp4 + (size_t)b*CELLS*5);
    #pragma unroll
    for (int a = 0; a < 2; a++) {
        if (w0[a] == 0.0f) continue;
        int ix = (int)p0f[a];
        #pragma unroll
        for (int c2 = 0; c2 < 2; c2++) {
            if (w1[c2] == 0.0f) continue;
            int iy = (int)p1f[c2];
            float wxy = w0[a]*w1[c2];
            float wag = wxy*wza;
            float* cp = hpb + (size_t)(iy*VRD + ix)*HPC;
            red_v4(cp, wxy*wze, wag, wag*sem[0], wag*sem[1]);
            if (agent) {
                red_v4(cp+4,  wag*sem[2],  wag*sem[3],  wag*sem[4],  wag*sem[5]);
                red_v4(cp+8,  wag*sem[6],  wag*sem[7],  wag*sem[8],  wag*sem[9]);
                red_v4(cp+12, wag*sem[10], wag*sem[11], wag*sem[12], wag*sem[13]);
                red_v4(cp+16, wag*sem[14], wag*sem[15], 0.0f, 0.0f);
            }
        }
    }
}

__device__ __forceinline__ void rotate_body(int t, int b, int grp, const float* __restrict__ poses) {
    int i0 = g_bbox[b][0], i1 = g_bbox[b][1], j0 = g_bbox[b][2], j1 = g_bbox[b][3];
    int w  = j1 - j0 + 1, h = i1 - i0 + 1;
    int li = t / w, lj = t % w;
    if (li >= h) return;
    int r = i0 + li, col = j0 + lj;

    float th = (90.0f - poses[b*3+2]) * 0.017453292519943295f;
    float ct = cosf(th), st = sinf(th);
    float x = (2.0f*col + 1.0f)/480.0f - 1.0f;
    float y = (2.0f*r   + 1.0f)/480.0f - 1.0f;
    float gx = ct*x - st*y;
    float gy = st*x + ct*y;
    float xs = (gx + 1.0f)*0.5f*479.0f;
    float ys = (gy + 1.0f)*0.5f*479.0f;
    float x0f = floorf(xs), y0f = floorf(ys);

    float wyv[2], wxv[2];
    int   lyi[2], lxi[2];
    #pragma unroll
    for (int k = 0; k < 2; k++) {
        float pyf = y0f + (float)k;
        int   yi  = (int)pyf;
        bool  ok  = (pyf >= 0.0f && pyf < 480.0f) && (yi >= 240 && yi < 340);
        wyv[k] = ok ? (1.0f - fabsf(ys - pyf)) : 0.0f;
        lyi[k] = min(max(yi - 240, 0), VRD-1);
        float pxf = x0f + (float)k;
        int   xi  = (int)pxf;
        bool  okx = (pxf >= 0.0f && pxf < 480.0f) && (xi >= 190 && xi < 290);
        wxv[k] = okx ? (1.0f - fabsf(xs - pxf)) : 0.0f;
        lxi[k] = min(max(xi - 190, 0), VRD-1);
    }

    float acc[6];
    #pragma unroll
    for (int c = 0; c < 6; c++) acc[c] = 0.0f;
    int q0 = (grp == 0) ? 0 : (grp == 1) ? 1 : 3;
    int q1 = q0 + 1;

    const float4* hpb = g_hp4 + (size_t)b*CELLS*5;
    #pragma unroll
    for (int dy = 0; dy < 2; dy++) {
        #pragma unroll
        for (int dx = 0; dx < 2; dx++) {
            float wgt = wxv[dx]*wyv[dy];
            const float4* cp = hpb + (size_t)(lyi[dy]*VRD + lxi[dx])*5;
            float4 ta = cp[q0], tb = cp[q1];
            if (grp == 0) {
                acc[0] += wgt * fminf(ta.y, 1.0f);
                acc[1] += wgt * fminf(ta.x, 1.0f);
                acc[2] += wgt * fminf(ta.z*0.2f, 1.0f);
                acc[3] += wgt * fminf(ta.w*0.2f, 1.0f);
                acc[4] += wgt * fminf(tb.x*0.2f, 1.0f);
                acc[5] += wgt * fminf(tb.y*0.2f, 1.0f);
            } else if (grp == 1) {
                acc[0] += wgt * fminf(ta.z*0.2f, 1.0f);
                acc[1] += wgt * fminf(ta.w*0.2f, 1.0f);
                acc[2] += wgt * fminf(tb.x*0.2f, 1.0f);
                acc[3] += wgt * fminf(tb.y*0.2f, 1.0f);
                acc[4] += wgt * fminf(tb.z*0.2f, 1.0f);
                acc[5] += wgt * fminf(tb.w*0.2f, 1.0f);
            } else {
                acc[0] += wgt * fminf(ta.x*0.2f, 1.0f);
                acc[1] += wgt * fminf(ta.y*0.2f, 1.0f);
                acc[2] += wgt * fminf(ta.z*0.2f, 1.0f);
                acc[3] += wgt * fminf(ta.w*0.2f, 1.0f);
                acc[4] += wgt * fminf(tb.x*0.2f, 1.0f);
                acc[5] += wgt * fminf(tb.y*0.2f, 1.0f);
            }
        }
    }
    float* rp = g_rotc + (size_t)b*TCH*RB2 + (size_t)(grp*6)*RB2 + (size_t)li*RB + lj;
    #pragma unroll
    for (int c = 0; c < 6; c++) rp[(size_t)c*RB2] = acc[c];
}

// copy one row: ch3 thread does full ch2/ch3 work; blended channels copy the
// row ONLY if it lies outside the translated row band (deferred rows -> k_final_rows)
__device__ __forceinline__ void copyA_body(int b, int cp_, int r, int t,
                                           const float* __restrict__ ml,
                                           const float* __restrict__ poses,
                                           float* __restrict__ out) {
    if (t >= 60) return;
    int c = (cp_ < 2) ? cp_ : cp_ + 1;
    int colA = t << 2, colB = colA + 240;
    size_t rbase = (size_t)r*MS;
    if (c == 3) {
        size_t m3 = ((size_t)b*NC + 3)*MS2 + rbase;
        size_t m2 = ((size_t)b*NC + 2)*MS2 + rbase;
        float4 vA = *(const float4*)(ml + m3 + colA);
        float4 vB = *(const float4*)(ml + m3 + colB);
        *(float4*)(out + m2 + colA) = vA;   // ch2 = pre-mask ch3
        *(float4*)(out + m2 + colB) = vB;
        float pxp = poses[b*3+0], pyp = poses[b*3+1];
        int rr = (int)(pyp*100.0f/5.0f);
        int cc = (int)(pxp*100.0f/5.0f);
        if (abs(r - rr) <= 1) {
            float* a = &vA.x; float* bb = &vB.x;
            #pragma unroll
            for (int p = 0; p < 4; p++) {
                if (abs(colA+p - cc) <= 1) a[p] = 1.0f;
                if (abs(colB+p - cc) <= 1) bb[p] = 1.0f;
            }
        }
        *(float4*)(out + m3 + colA) = vA;
        *(float4*)(out + m3 + colB) = vB;
        return;
    }
    if (r >= g_bbox[b][4] && r <= g_bbox[b][5]) return;   // deferred to k_final_rows
    size_t mbase = ((size_t)b*NC + c)*MS2 + rbase;
    float4 mA = *(const float4*)(ml + mbase + colA);
    float4 mB = *(const float4*)(ml + mbase + colB);
    *(float4*)(out + mbase + colA) = mA;
    *(float4*)(out + mbase + colB) = mB;
}

// k2: splat || copy row-groups 0..59
__global__ void __launch_bounds__(256) k_splat_copy(const float* __restrict__ obs,
                                                    const float* __restrict__ maps_last,
                                                    const float* __restrict__ poses,
                                                    float* __restrict__ out,
                                                    float f_cam) {
    int gid = blockIdx.x;
    if (gid < SPLAT_BLKS) {
        int tid = threadIdx.x + 64*threadIdx.y;
        splat_body(gid*256 + tid, obs, f_cam);
        return;
    }
    int cid = gid - SPLAT_BLKS;
    int xb  = cid % 60;
    int cp_ = (cid / 60) % 19;
    int b   = cid / (60*19);
    copyA_body(b, cp_, xb*4 + threadIdx.y, threadIdx.x, maps_last, poses, out);
}

// k3: rotate || copy row-groups 60..119
__global__ void __launch_bounds__(256) k_rot_copy(const float* __restrict__ maps_last,
                                                  const float* __restrict__ poses,
                                                  float* __restrict__ out) {
    int gid = blockIdx.x;
    if (gid < ROT_BLKS) {
        int tid = threadIdx.x + 64*threadIdx.y;
        int bx  = gid % 100;
        int b   = (gid / 100) % NB;
        int grp = gid / 800;
        rotate_body(bx*256 + tid, b, grp, poses);
        return;
    }
    int cid = gid - ROT_BLKS;
    int xb  = 60 + cid % 60;
    int cp_ = (cid / 60) % 19;
    int b   = cid / (60*19);
    copyA_body(b, cp_, xb*4 + threadIdx.y, threadIdx.x, maps_last, poses, out);
}

// k4: proven fused final logic restricted to rows inside the translated band.
// grid(40, 18, 8), block(64,4). cp_ 0..17 -> out channel {0,1,4..19}; rc = cp_.
__global__ void __launch_bounds__(256) k_final_rows(const float* __restrict__ maps_last,
                        const float* __restrict__ poses,
                        float* __restrict__ out) {
    int t = threadIdx.x;
    if (t >= 60) return;
    int b   = blockIdx.z;
    int ti0 = g_bbox[b][4], ti1 = g_bbox[b][5];
    int r   = ti0 + blockIdx.x*4 + threadIdx.y;
    if (r > ti1) return;
    int cp_ = blockIdx.y;
    int c   = (cp_ < 2) ? cp_ : cp_ + 2;      // {0,1,4..19}
    int colA = t << 2, colB = colA + 240;

    float pxp = poses[b*3+0], pyp = poses[b*3+1];
    size_t rbase = (size_t)r*MS;
    size_t mbase = ((size_t)b*NC + c)*MS2 + rbase;
    float4 mA = *(const float4*)(maps_last + mbase + colA);
    float4 mB = *(const float4*)(maps_last + mbase + colB);

    int tj0 = g_bbox[b][6], tj1 = g_bbox[b][7];
    bool actA = !(colA+3 < tj0 || colA > tj1);
    bool actB = !(colB+3 < tj0 || colB > tj1);

    if (!actA && !actB) {
        *(float4*)(out + mbase + colA) = mA;
        *(float4*)(out + mbase + colB) = mB;
        return;
    }

    float stx = -((pxp*100.0f)/5.0f - 240.0f)/240.0f;
    float sty = -((pyp*100.0f)/5.0f - 240.0f)/240.0f;

    float ys  = ((2.0f*r + 1.0f)/480.0f + sty)*0.5f*479.0f;
    float y0f = floorf(ys);
    float wy0 = (y0f + 1.0f) - ys;
    float wy1 = ys - y0f;
    int   ry0 = (int)y0f, ry1 = ry0 + 1;
    int i0 = g_bbox[b][0], i1 = g_bbox[b][1], j0 = g_bbox[b][2], j1 = g_bbox[b][3];
    bool vy0 = (y0f      >= 0.0f && y0f      < 480.0f) && ry0 >= i0 && ry0 <= i1;
    bool vy1 = (y0f+1.0f >= 0.0f && y0f+1.0f < 480.0f) && ry1 >= i0 && ry1 <= i1;

    const float* base = g_rotc + ((size_t)b*TCH + cp_)*RB2;
    int ly0 = min(max(ry0 - i0, 0), RB-1);
    int ly1 = min(max(ry1 - i0, 0), RB-1);
    const float* row0 = base + (size_t)ly0*RB;
    const float* row1 = base + (size_t)ly1*RB;
    const float XSTEP = 479.0f/480.0f;
    bool anyY = vy0 || vy1;

    float4 oA = mA, oB = mB;
    #pragma unroll
    for (int hh = 0; hh < 2; hh++) {
        bool act = hh ? actB : actA;
        if (!act || !anyY) continue;
        int c0 = hh ? colB : colA;
        float4* o = hh ? &oB : &oA;
        float xs_base = ((2.0f*c0 + 1.0f)/480.0f + stx)*0.5f*479.0f;
        float* of = &o->x;
        #pragma unroll
        for (int p = 0; p < 4; p++) {
            float xs  = fmaf((float)p, XSTEP, xs_base);
            float x0f = floorf(xs);
            float wx1 = xs - x0f;
            float wx0 = 1.0f - wx1;
            int   cx0 = (int)x0f;
            bool vx0 = (x0f      >= 0.0f && x0f      < 480.0f) && cx0   >= j0 && cx0   <= j1;
            bool vx1 = (x0f+1.0f >= 0.0f && x0f+1.0f < 480.0f) && cx0+1 >= j0 && cx0+1 <= j1;
            if (!(vx0 || vx1)) continue;
            int lx0 = min(max(cx0 - j0, 0), RB-2);
            float acc = 0.0f;
            if (vy0) {
                if (vx0) acc += wx0*wy0*row0[lx0];
                if (vx1) acc += wx1*wy0*row0[lx0+1];
            }
            if (vy1) {
                if (vx0) acc += wx0*wy1*row1[lx0];
                if (vx1) acc += wx1*wy1*row1[lx0+1];
            }
            of[p] = fmaxf(of[p], acc);
        }
    }
    *(float4*)(out + mbase + colA) = oA;
    *(float4*)(out + mbase + colB) = oB;
}

extern "C" void kernel_launch(void* const* d_in, const int* in_sizes, int n_in,
                              void* d_out, int out_size) {
    const float* obs       = (const float*)d_in[0];   // (8,20,120,160)
    const float* maps_last = (const float*)d_in[1];   // (8,20,480,480)
    const float* poses     = (const float*)d_in[2];   // (8,3)
    float* out = (float*)d_out;                       // (8,20,480,480)

    float f_cam = (float)((double)FW / 2.0 / tan(79.0/2.0 * 3.14159265358979323846/180.0));

    k_bbox_zero <<<((NB*CELLS*5) + 255)/256, 256>>>(poses);
    k_splat_copy<<<SPLAT_BLKS + COPYH_BLKS, dim3(64,4)>>>(obs, maps_last, poses, out, f_cam);
    k_rot_copy  <<<ROT_BLKS + COPYH_BLKS,   dim3(64,4)>>>(maps_last, poses, out);
    k_final_rows<<<dim3(40, TCH, NB), dim3(64,4)>>>(maps_last, poses, out);
}